// round 5
// baseline (speedup 1.0000x reference)
#include <cuda_runtime.h>

// Problem constants (fixed by setup_inputs): B=64, T=8000, M=80
#define B_  64
#define T_  8000
#define M_  80
#define MG  (M_ / 2)             // 40 mel-pairs: each thread owns 2 adjacent mels
#define TC  50                   // timesteps per chunk (L2-resident between passes)
#define NC  (T_ / TC)            // 160 chunks
#define NTHREADS (NC * B_ * MG)  // 409600 threads
#define THREADS 256
#define EPS 1e-6f
#define SENTINEL 0xFFFFFFFFu     // -NaN bits; published values are finite -> never collide
#define CSTRIDE (B_ * MG)        // slot stride between consecutive chunks

// Per-(chunk,b,mel-pair) slots: {lane0, lane1} packed in 64 bits (single-copy atomic).
// g_loc = local chunk endpoints, g_inc = inclusive endpoints. Reset to 0xFF per launch.
__device__ unsigned long long g_loc[NC * B_ * MG];
__device__ unsigned long long g_inc[NC * B_ * MG];
// Precomputed per-mel parameters.
__device__ float4 g_pow[M_];   // (-alpha, r, delta, delta^r)
__device__ float4 g_ema[M_];   // (s, 1-s, (1-s)^TC, 0)

__device__ __forceinline__ float fast_log2(float x) {
    float y; asm("lg2.approx.f32 %0, %1;" : "=f"(y) : "f"(x)); return y;
}
__device__ __forceinline__ float fast_exp2(float x) {
    float y; asm("ex2.approx.f32 %0, %1;" : "=f"(y) : "f"(x)); return y;
}
__device__ __forceinline__ unsigned long long ld_relaxed64(const unsigned long long* p) {
    unsigned long long v;
    asm volatile("ld.relaxed.gpu.b64 %0, [%1];" : "=l"(v) : "l"(p) : "memory");
    return v;
}
__device__ __forceinline__ void st_release64(unsigned long long* p, unsigned long long v) {
    asm volatile("st.release.gpu.b64 [%0], %1;" :: "l"(p), "l"(v) : "memory");
}
__device__ __forceinline__ void st_stream2(float* p, float a, float b) {
    asm volatile("st.global.cs.v2.f32 [%0], {%1, %2};" :: "l"(p), "f"(a), "f"(b) : "memory");
}
__device__ __forceinline__ unsigned long long pack2(float a, float b) {
    return (unsigned long long)__float_as_uint(a) |
           ((unsigned long long)__float_as_uint(b) << 32);
}
__device__ __forceinline__ float lo_f(unsigned long long v) { return __uint_as_float((unsigned)v); }
__device__ __forceinline__ float hi_f(unsigned long long v) { return __uint_as_float((unsigned)(v >> 32)); }

__global__ void pcen_params_kernel(const float* __restrict__ log_s,
                                   const float* __restrict__ log_alpha,
                                   const float* __restrict__ log_delta,
                                   const float* __restrict__ log_r)
{
    const int m = threadIdx.x;
    if (m < M_) {
        const float s     = expf(log_s[m]);
        const float om    = 1.0f - s;
        const float alpha = expf(log_alpha[m]);
        const float delta = expf(log_delta[m]);
        const float r     = expf(log_r[m]);
        g_pow[m] = make_float4(-alpha, r, delta, powf(delta, r));
        g_ema[m] = make_float4(s, om, powf(om, (float)TC), 0.0f);
    }
}

__global__ __launch_bounds__(THREADS)
void pcen_flat_kernel(const float* __restrict__ x, float* __restrict__ out)
{
    const int gtid = blockIdx.x * THREADS + threadIdx.x;
    const int mg = gtid % MG;
    const int bc = gtid / MG;
    const int b  = bc % B_;
    const int c  = bc / B_;      // chunk-major: low block ids = early chunks, scheduled first

    const int  m0 = 2 * mg;
    const long gbase = ((long)b * T_ + (long)c * TC) * M_ + m0;
    const float2* __restrict__ xp = (const float2*)(x + gbase);  // per-t stride = MG float2

    const float4 E0 = g_ema[m0],     E1 = g_ema[m0 + 1];
    const float4 P0 = g_pow[m0],     P1 = g_pow[m0 + 1];
    const float s0 = E0.x, om0 = E0.y, pTc0 = E0.z;
    const float s1 = E1.x, om1 = E1.y, pTc1 = E1.z;

    // ---- S1: local scan endpoints; even/odd split halves serial FMA depth ----
    // lend = s*(om*A + B),  A = sum om2^{K-1-k} x_{2k},  B = sum om2^{K-1-k} x_{2k+1}
    float A0 = 0.f, Bv0 = 0.f, A1 = 0.f, Bv1 = 0.f;
    const float om2_0 = om0 * om0, om2_1 = om1 * om1;
    #pragma unroll 5
    for (int k = 0; k < TC / 2; ++k) {
        const float2 xe = __ldg(xp + (2 * k)     * MG);
        const float2 xo = __ldg(xp + (2 * k + 1) * MG);
        A0  = fmaf(om2_0, A0,  xe.x);  Bv0 = fmaf(om2_0, Bv0, xo.x);
        A1  = fmaf(om2_1, A1,  xe.y);  Bv1 = fmaf(om2_1, Bv1, xo.y);
    }
    const float l0 = s0 * fmaf(om0, A0, Bv0);
    const float l1 = s1 * fmaf(om1, A1, Bv1);

    // ---- publish local endpoints immediately ----
    const long sidx = (long)b * MG + mg;
    st_release64(&g_loc[sidx + (long)c * CSTRIDE], pack2(l0, l1));

    // ---- lookback: fast-path probe of predecessor inclusive; else backward walk ----
    float c0 = 0.f, c1 = 0.f;
    if (c > 0) {
        const unsigned long long iv = ld_relaxed64(&g_inc[sidx + (long)(c - 1) * CSTRIDE]);
        if ((unsigned)iv != SENTINEL) {
            c0 = lo_f(iv); c1 = hi_f(iv);               // common case: one L2 load
        } else {
            float a0 = 0.f, a1 = 0.f, w0 = 1.f, w1 = 1.f;
            for (int j = c - 1; ; --j) {
                const unsigned long long jv = ld_relaxed64(&g_inc[sidx + (long)j * CSTRIDE]);
                if ((unsigned)jv != SENTINEL) {          // inclusive found -> terminate
                    c0 = fmaf(w0, lo_f(jv), a0);
                    c1 = fmaf(w1, hi_f(jv), a1);
                    break;
                }
                unsigned long long lv = ld_relaxed64(&g_loc[sidx + (long)j * CSTRIDE]);
                while ((unsigned)lv == SENTINEL) {       // local not yet published: poll
                    __nanosleep(32);
                    lv = ld_relaxed64(&g_loc[sidx + (long)j * CSTRIDE]);
                }
                a0 = fmaf(w0, lo_f(lv), a0);
                a1 = fmaf(w1, hi_f(lv), a1);
                w0 *= pTc0; w1 *= pTc1;
                if (j == 0) { c0 = a0; c1 = a1; break; }
            }
        }
    }

    // ---- publish inclusive endpoints (accelerates all successors) ----
    st_release64(&g_inc[sidx + (long)c * CSTRIDE],
                 pack2(fmaf(pTc0, c0, l0), fmaf(pTc1, c1, l1)));

    // ---- S2 + output fused: rescan from true carry (x re-read hits L2), compress ----
    float mr0 = c0, mr1 = c1;
    float* const op = out + gbase;
    #pragma unroll 5
    for (int t = 0; t < TC; ++t) {
        const float2 xv = __ldg(xp + t * MG);
        mr0 = fmaf(om0, mr0, s0 * xv.x);
        mr1 = fmaf(om1, mr1, s1 * xv.y);
        const float v0 = xv.x * fast_exp2(P0.x * fast_log2(mr0 + EPS));
        const float v1 = xv.y * fast_exp2(P1.x * fast_log2(mr1 + EPS));
        const float o0 = fast_exp2(P0.y * fast_log2(v0 + P0.z)) - P0.w;
        const float o1 = fast_exp2(P1.y * fast_log2(v1 + P1.z)) - P1.w;
        st_stream2(op + (long)t * M_, o0, o1);           // evict-first: keep x in L2
    }
}

extern "C" void kernel_launch(void* const* d_in, const int* in_sizes, int n_in,
                              void* d_out, int out_size)
{
    const float* x  = (const float*)d_in[0];
    const float* ls = (const float*)d_in[1];
    const float* la = (const float*)d_in[2];
    const float* ld = (const float*)d_in[3];
    const float* lr = (const float*)d_in[4];
    float* out = (float*)d_out;

    void* p = nullptr;
    cudaGetSymbolAddress(&p, g_loc);
    cudaMemsetAsync(p, 0xFF, NC * B_ * MG * sizeof(unsigned long long), 0);
    cudaGetSymbolAddress(&p, g_inc);
    cudaMemsetAsync(p, 0xFF, NC * B_ * MG * sizeof(unsigned long long), 0);

    pcen_params_kernel<<<1, 128>>>(ls, la, ld, lr);
    pcen_flat_kernel<<<NTHREADS / THREADS, THREADS>>>(x, out);
}

// round 6
// speedup vs baseline: 1.1286x; 1.1286x over previous
#include <cuda_runtime.h>

// Problem constants (fixed by setup_inputs): B=64, T=8000, M=80
#define B_  64
#define T_  8000
#define M_  80
#define TC  50                   // timesteps per chunk (L2-resident between S1 and S2)
#define NC  (T_ / TC)            // 160 chunks
#define NTHREADS (NC * B_ * M_)  // 819200 threads: one per (chunk, batch, mel)
#define THREADS 256
#define EPS 1e-6f
#define SENTINEL 0xFFFFFFFFu     // -NaN bits; published values are finite nonneg -> no collision
#define CSTRIDE (B_ * M_)        // slot stride between consecutive chunks

// Per-(chunk,b,m) slot: low 32 = local endpoint, high 32 = inclusive endpoint.
// Reset to 0xFF via cudaMemsetAsync each launch. 64-bit stores are single-copy atomic.
__device__ unsigned long long g_slot[NC * B_ * M_];
// Precomputed per-mel parameters.
__device__ float4 g_pow[M_];   // (-alpha, r, delta, delta^r)
__device__ float4 g_ema[M_];   // (s, 1-s, (1-s)^TC, 0)

__device__ __forceinline__ float fast_log2(float x) {
    float y; asm("lg2.approx.f32 %0, %1;" : "=f"(y) : "f"(x)); return y;
}
__device__ __forceinline__ float fast_exp2(float x) {
    float y; asm("ex2.approx.f32 %0, %1;" : "=f"(y) : "f"(x)); return y;
}
__device__ __forceinline__ unsigned long long ld_relaxed64(const unsigned long long* p) {
    unsigned long long v;
    asm volatile("ld.relaxed.gpu.b64 %0, [%1];" : "=l"(v) : "l"(p) : "memory");
    return v;
}
__device__ __forceinline__ void st_release64(unsigned long long* p, unsigned long long v) {
    asm volatile("st.release.gpu.b64 [%0], %1;" :: "l"(p), "l"(v) : "memory");
}
__device__ __forceinline__ void st_stream(float* p, float v) {
    asm volatile("st.global.cs.f32 [%0], %1;" :: "l"(p), "f"(v) : "memory");
}
__device__ __forceinline__ float lo_f(unsigned long long v) { return __uint_as_float((unsigned)v); }
__device__ __forceinline__ float hi_f(unsigned long long v) { return __uint_as_float((unsigned)(v >> 32)); }

__global__ void pcen_params_kernel(const float* __restrict__ log_s,
                                   const float* __restrict__ log_alpha,
                                   const float* __restrict__ log_delta,
                                   const float* __restrict__ log_r)
{
    const int m = threadIdx.x;
    if (m < M_) {
        const float s     = expf(log_s[m]);
        const float om    = 1.0f - s;
        const float alpha = expf(log_alpha[m]);
        const float delta = expf(log_delta[m]);
        const float r     = expf(log_r[m]);
        g_pow[m] = make_float4(-alpha, r, delta, powf(delta, r));
        g_ema[m] = make_float4(s, om, powf(om, (float)TC), 0.0f);
    }
}

__global__ __launch_bounds__(THREADS, 8)   // cap regs at 32 -> 2048 threads/SM
void pcen_flat_kernel(const float* __restrict__ x, float* __restrict__ out)
{
    const int gtid = blockIdx.x * THREADS + threadIdx.x;
    const int m  = gtid % M_;
    const int bc = gtid / M_;
    const int b  = bc % B_;
    const int c  = bc / B_;      // chunk-major: low block ids = early chunks, scheduled first

    // All indices fit in int32 (max 40.96M) -> cheaper addressing, fewer regs.
    const int gbase = (b * T_ + c * TC) * M_ + m;
    const float* __restrict__ xp = x + gbase;

    const float4 E = g_ema[m];   // s, om, om^TC
    const float4 P = g_pow[m];   // -alpha, r, delta, delta^r
    const float s = E.x, om = E.y, powTc = E.z;

    // ---- S1: local scan endpoint; even/odd accumulators halve serial FMA depth ----
    // lend = s*(om*A + Bv):  A = sum om2^{24-k} x_{2k},  Bv = sum om2^{24-k} x_{2k+1}
    float A = 0.f, Bv = 0.f;
    const float om2 = om * om;
    #pragma unroll 5
    for (int k = 0; k < TC / 2; ++k) {
        const float xe = __ldg(xp + (2 * k)     * M_);
        const float xo = __ldg(xp + (2 * k + 1) * M_);
        A  = fmaf(om2, A,  xe);
        Bv = fmaf(om2, Bv, xo);
    }
    const float lend  = s * fmaf(om, A, Bv);
    const unsigned lb = __float_as_uint(lend);

    // ---- publish local endpoint immediately ----
    unsigned long long* const slot = &g_slot[c * CSTRIDE + b * M_ + m];
    st_release64(slot, (unsigned long long)lb | ((unsigned long long)SENTINEL << 32));

    // ---- lookback: fast-path probe of predecessor inclusive; else backward walk ----
    float carry = 0.0f;
    if (c > 0) {
        unsigned long long v = ld_relaxed64(slot - CSTRIDE);
        if ((unsigned)(v >> 32) != SENTINEL) {
            carry = hi_f(v);                         // common case: one L2 load
        } else {
            float acc = 0.f, w = 1.f;
            int j = c - 1;
            while (true) {
                unsigned lo = (unsigned)v, hi = (unsigned)(v >> 32);
                while (lo == SENTINEL) {             // local not yet published: poll
                    __nanosleep(32);
                    v = ld_relaxed64(&g_slot[j * CSTRIDE + b * M_ + m]);
                    lo = (unsigned)v; hi = (unsigned)(v >> 32);
                }
                if (hi != SENTINEL) {                // inclusive found -> terminate walk
                    carry = fmaf(w, __uint_as_float(hi), acc);
                    break;
                }
                acc = fmaf(w, __uint_as_float(lo), acc);
                w  *= powTc;
                if (--j < 0) { carry = acc; break; }
                v = ld_relaxed64(&g_slot[j * CSTRIDE + b * M_ + m]);
            }
        }
    }

    // ---- publish inclusive endpoint (accelerates all successors) ----
    const float incl = fmaf(powTc, carry, lend);
    st_release64(slot, (unsigned long long)lb |
                       ((unsigned long long)__float_as_uint(incl) << 32));

    // ---- S2 + output fused: rescan from true carry (x re-read hits L2), compress ----
    float mr = carry;
    float* const op = out + gbase;
    #pragma unroll 5
    for (int t = 0; t < TC; ++t) {
        const float xv = __ldg(xp + t * M_);
        mr = fmaf(om, mr, s * xv);
        const float vv = xv * fast_exp2(P.x * fast_log2(mr + EPS));  // x*(m+eps)^-alpha
        const float oo = fast_exp2(P.y * fast_log2(vv + P.z)) - P.w; // (v+delta)^r - delta^r
        st_stream(op + t * M_, oo);                                  // evict-first store
    }
}

extern "C" void kernel_launch(void* const* d_in, const int* in_sizes, int n_in,
                              void* d_out, int out_size)
{
    const float* x  = (const float*)d_in[0];
    const float* ls = (const float*)d_in[1];
    const float* la = (const float*)d_in[2];
    const float* ld = (const float*)d_in[3];
    const float* lr = (const float*)d_in[4];
    float* out = (float*)d_out;

    void* p = nullptr;
    cudaGetSymbolAddress(&p, g_slot);
    cudaMemsetAsync(p, 0xFF, NC * B_ * M_ * sizeof(unsigned long long), 0);

    pcen_params_kernel<<<1, 128>>>(ls, la, ld, lr);
    pcen_flat_kernel<<<NTHREADS / THREADS, THREADS>>>(x, out);
}

// round 8
// speedup vs baseline: 1.1579x; 1.0260x over previous
#include <cuda_runtime.h>

// Problem constants (fixed by setup_inputs): B=64, T=8000, M=80
#define B_  64
#define T_  8000
#define M_  80
#define TC  32                   // timesteps per chunk; x chunk staged in SMEM
#define NC  (T_ / TC)            // 250 chunks
#define NTHREADS (NC * B_ * M_)  // 1,280,000 threads: one per (chunk, batch, mel)
#define THREADS 256
#define EPS 1e-6f
#define SENTINEL 0xFFFFFFFFu     // -NaN bits; published values are finite -> no collision
#define CSTRIDE (B_ * M_)        // slot stride between consecutive chunks
#define LBATCH 4                 // lookback walk MLP batch

// Per-(chunk,b,m) slot: low 32 = local endpoint, high 32 = inclusive endpoint.
// Reset to 0xFF via cudaMemsetAsync each launch. Aligned 64-bit accesses are single-copy atomic.
__device__ unsigned long long g_slot[NC * B_ * M_];
// Precomputed per-mel parameters.
__device__ float4 g_pow[M_];   // (-alpha, r, delta, delta^r)
__device__ float4 g_ema[M_];   // (s, 1-s, (1-s)^TC, 0)

__device__ __forceinline__ float fast_log2(float x) {
    float y; asm("lg2.approx.f32 %0, %1;" : "=f"(y) : "f"(x)); return y;
}
__device__ __forceinline__ float fast_exp2(float x) {
    float y; asm("ex2.approx.f32 %0, %1;" : "=f"(y) : "f"(x)); return y;
}
__device__ __forceinline__ unsigned long long ld_relaxed64(const unsigned long long* p) {
    unsigned long long v;
    asm volatile("ld.relaxed.gpu.b64 %0, [%1];" : "=l"(v) : "l"(p) : "memory");
    return v;
}
__device__ __forceinline__ void st_release64(unsigned long long* p, unsigned long long v) {
    asm volatile("st.release.gpu.b64 [%0], %1;" :: "l"(p), "l"(v) : "memory");
}
__device__ __forceinline__ void st_stream(float* p, float v) {
    asm volatile("st.global.cs.f32 [%0], %1;" :: "l"(p), "f"(v) : "memory");
}

__global__ void pcen_params_kernel(const float* __restrict__ log_s,
                                   const float* __restrict__ log_alpha,
                                   const float* __restrict__ log_delta,
                                   const float* __restrict__ log_r)
{
    const int m = threadIdx.x;
    if (m < M_) {
        const float s     = expf(log_s[m]);
        const float om    = 1.0f - s;
        const float alpha = expf(log_alpha[m]);
        const float delta = expf(log_delta[m]);
        const float r     = expf(log_r[m]);
        g_pow[m] = make_float4(-alpha, r, delta, powf(delta, r));
        g_ema[m] = make_float4(s, om, powf(om, (float)TC), 0.0f);
    }
}

extern __shared__ float s_x[];   // [TC][THREADS] transposed stash: conflict-free

__global__ __launch_bounds__(THREADS)
void pcen_flat_kernel(const float* __restrict__ x, float* __restrict__ out)
{
    const int tid  = threadIdx.x;
    const int gtid = blockIdx.x * THREADS + tid;
    const int m  = gtid % M_;
    const int bc = gtid / M_;
    const int b  = bc % B_;
    const int c  = bc / B_;      // chunk-major: low block ids = early chunks, scheduled first

    const int bm    = b * M_ + m;                   // slot offset within a chunk
    const int gbase = (b * T_ + c * TC) * M_ + m;   // fits int32 (max ~41M)
    const float* __restrict__ xp = x + gbase;

    const float4 E = g_ema[m];   // s, om, om^TC
    const float4 P = g_pow[m];   // -alpha, r, delta, delta^r
    const float s = E.x, om = E.y, powTc = E.z;

    // ---- S1: load chunk from DRAM ONCE, stash in SMEM, scan endpoint ----
    // Even/odd accumulator split halves the serial FMA depth.
    float A = 0.f, Bv = 0.f;
    const float om2 = om * om;
    #pragma unroll
    for (int k = 0; k < TC / 2; ++k) {
        const float xe = __ldg(xp + (2 * k)     * M_);
        const float xo = __ldg(xp + (2 * k + 1) * M_);
        s_x[(2 * k)     * THREADS + tid] = xe;
        s_x[(2 * k + 1) * THREADS + tid] = xo;
        A  = fmaf(om2, A,  xe);
        Bv = fmaf(om2, Bv, xo);
    }
    const float lend  = s * fmaf(om, A, Bv);
    const unsigned lb = __float_as_uint(lend);

    // ---- publish local endpoint immediately ----
    unsigned long long* const slot = &g_slot[c * CSTRIDE + bm];
    st_release64(slot, (unsigned long long)lb | ((unsigned long long)SENTINEL << 32));

    // ---- lookback: probe predecessor inclusive (fast path), else batched walk ----
    // Explicit chunk-index addressing: predecessor chunk jj's slot is g_slot[jj*CSTRIDE + bm].
    float carry = 0.0f;
    if (c > 0) {
        unsigned long long v0 = ld_relaxed64(&g_slot[(c - 1) * CSTRIDE + bm]);
        if ((unsigned)(v0 >> 32) != SENTINEL) {
            carry = __uint_as_float((unsigned)(v0 >> 32));   // common case: one L2 load
        } else {
            float acc = 0.f, w = 1.f;
            int j = c - 1;                                   // next chunk to consume
            bool done = false;
            while (!done) {
                unsigned long long v[LBATCH];
                const int n = (j + 1 < LBATCH) ? (j + 1) : LBATCH;
                #pragma unroll
                for (int k = 0; k < LBATCH; ++k)             // independent L2 loads (MLP)
                    if (k < n) v[k] = ld_relaxed64(&g_slot[(j - k) * CSTRIDE + bm]);
                for (int k = 0; k < n; ++k) {                // consume in order: j, j-1, ...
                    const int jj = j - k;
                    unsigned long long pv = v[k];
                    unsigned lo = (unsigned)pv, hi = (unsigned)(pv >> 32);
                    while (lo == SENTINEL) {                 // local not published yet: poll
                        __nanosleep(32);
                        pv = ld_relaxed64(&g_slot[jj * CSTRIDE + bm]);
                        lo = (unsigned)pv; hi = (unsigned)(pv >> 32);
                    }
                    if (hi != SENTINEL) {                    // inclusive found -> terminate
                        carry = fmaf(w, __uint_as_float(hi), acc);
                        done = true;
                        break;
                    }
                    acc = fmaf(w, __uint_as_float(lo), acc); // weighted local
                    w  *= powTc;
                }
                if (!done) {
                    j -= n;
                    if (j < 0) { carry = acc; done = true; } // reached chunk 0 (state 0)
                }
            }
        }
    }

    // ---- publish inclusive endpoint (accelerates all successors) ----
    st_release64(slot, (unsigned long long)lb |
                       ((unsigned long long)__float_as_uint(fmaf(powTc, carry, lend)) << 32));

    // ---- S2 + output fused: rescan from SMEM stash (29-cyc LDS, zero L2), compress ----
    float mr = carry;
    float* const op = out + gbase;
    #pragma unroll 4
    for (int t = 0; t < TC; ++t) {
        const float xv = s_x[t * THREADS + tid];
        mr = fmaf(om, mr, s * xv);
        const float vv = xv * fast_exp2(P.x * fast_log2(mr + EPS));  // x*(m+eps)^-alpha
        const float oo = fast_exp2(P.y * fast_log2(vv + P.z)) - P.w; // (v+delta)^r - delta^r
        st_stream(op + t * M_, oo);                                  // evict-first store
    }
}

extern "C" void kernel_launch(void* const* d_in, const int* in_sizes, int n_in,
                              void* d_out, int out_size)
{
    const float* x  = (const float*)d_in[0];
    const float* ls = (const float*)d_in[1];
    const float* la = (const float*)d_in[2];
    const float* ld = (const float*)d_in[3];
    const float* lr = (const float*)d_in[4];
    float* out = (float*)d_out;

    void* p = nullptr;
    cudaGetSymbolAddress(&p, g_slot);
    cudaMemsetAsync(p, 0xFF, NC * B_ * M_ * sizeof(unsigned long long), 0);

    const int smem_bytes = TC * THREADS * (int)sizeof(float);   // 32 KB
    cudaFuncSetAttribute(pcen_flat_kernel,
                         cudaFuncAttributeMaxDynamicSharedMemorySize, smem_bytes);

    pcen_params_kernel<<<1, 128>>>(ls, la, ld, lr);
    pcen_flat_kernel<<<NTHREADS / THREADS, THREADS, smem_bytes>>>(x, out);
}